// round 16
// baseline (speedup 1.0000x reference)
#include <cuda_runtime.h>
#include <cuda_fp16.h>
#include <math.h>
#include <stdint.h>

#define BB 4
#define CC 64
#define NN 4096
#define TQa 128
#define TKa 64
#define NTILE (NN / TKa)      // 64 tiles per batch
#define NSPLIT 2
#define TPS (NTILE / NSPLIT)  // 32 tiles per split

// Scratch (__device__ globals). Everything fp16 fragment-packed.
__device__ uint32_t  g_wph[3 * 2048];           // wq/wk/wv in K-tile B-frag layout
__device__ __half    g_qh[BB * NN * CC];        // (b, n, c) token-major fp16
__device__ uint32_t  g_kph[BB * NTILE * 2048];  // packed K tiles (half2 regs)
__device__ uint32_t  g_vph[BB * NTILE * 2048];  // packed V tiles
__device__ float     g_po[NSPLIT * BB * CC * NN];  // unnormalized O partials
__device__ float     g_pl[NSPLIT * BB * NN];       // row-sum partials

// ---------------------------------------------------------------------------
__device__ __forceinline__ float ex2(float x) {
    float y;
    asm("ex2.approx.ftz.f32 %0, %1;" : "=f"(y) : "f"(x));
    return y;
}
__device__ __forceinline__ uint32_t h2(float lo, float hi) {
    __half2 h = __floats2half2_rn(lo, hi);
    return *(uint32_t*)&h;
}
__device__ __forceinline__ uint32_t smem_u32(const void* p) {
    uint32_t a;
    asm("{ .reg .u64 t; cvta.to.shared.u64 t, %1; cvt.u32.u64 %0, t; }" : "=r"(a) : "l"(p));
    return a;
}
__device__ __forceinline__ void cp16(uint32_t dst, const void* src) {
    asm volatile("cp.async.cg.shared.global [%0], [%1], 16;" :: "r"(dst), "l"(src));
}
__device__ __forceinline__ void cp_commit() { asm volatile("cp.async.commit_group;"); }
__device__ __forceinline__ void cp_wait0() { asm volatile("cp.async.wait_group 0;"); }

// fp16 m16n8k16 mma, fp32 accumulate
__device__ __forceinline__ void mma16(float* d, const uint32_t* a,
                                      uint32_t b0, uint32_t b1) {
    asm volatile(
        "mma.sync.aligned.m16n8k16.row.col.f32.f16.f16.f32 "
        "{%0,%1,%2,%3}, {%4,%5,%6,%7}, {%8,%9}, {%0,%1,%2,%3};"
        : "+f"(d[0]), "+f"(d[1]), "+f"(d[2]), "+f"(d[3])
        : "r"(a[0]), "r"(a[1]), "r"(a[2]), "r"(a[3]), "r"(b0), "r"(b1));
}

// ---------------------------------------------------------------------------
// Kernel 0: pack weights once into B-frag layout (n = out-ch o, k = in-ch c).
// ---------------------------------------------------------------------------
__global__ void __launch_bounds__(256) wpack_kernel(
    const float* __restrict__ wq, const float* __restrict__ wk,
    const float* __restrict__ wv)
{
    int i = blockIdx.x * 256 + threadIdx.x;   // 12288 total
    int m = i >> 12, rem = i & 4095;
    int o = rem >> 6, c = rem & 63;
    const float* w = (m == 0) ? wq : (m == 1) ? wk : wv;
    int s = c >> 4, t = o >> 3;
    int lamk = 4 * (o & 7) + ((c >> 1) & 3);
    int breg = (c >> 3) & 1;
    int u32i = ((s * 4 + (t >> 1)) * 32 + lamk) * 4 + (t & 1) * 2 + breg;
    ((__half*)g_wph)[m * 4096 + u32i * 2 + (c & 1)] = __float2half_rn(w[o * 64 + c]);
}

// ---------------------------------------------------------------------------
// Kernel 1: tensor-core QKV projection. 128 threads, warp = 16 tokens.
// SMEM (u32): Xh[2048] (token-major half2) | Wp[6144]  = 32 KB
// ---------------------------------------------------------------------------
__global__ void __launch_bounds__(128) proj_kernel(
    const float* __restrict__ x,
    const float* __restrict__ bq, const float* __restrict__ bk,
    const float* __restrict__ bv)
{
    extern __shared__ uint32_t smu[];
    uint32_t* Xh = smu;           // 2048 u32
    uint32_t* Wp = smu + 2048;    // 6144 u32
    const uint32_t smW = smem_u32(Wp);

    const int b = blockIdx.y, tile = blockIdx.x, n0 = tile * 64;
    const int tid = threadIdx.x, w = tid >> 5, lam = tid & 31;
    const int g = lam >> 2, tau = lam & 3;

    // stage packed weights (24 KB = 1536 uint4)
    #pragma unroll
    for (int r = 0; r < 12; r++) {
        int i = tid + 128 * r;
        cp16(smW + i * 16, (const uint4*)g_wph + i);
    }
    cp_commit();

    // stage X -> fp16 token-major SMEM
    __half* Xsh = (__half*)Xh;
    #pragma unroll
    for (int r = 0; r < 8; r++) {
        int idx4 = tid + 128 * r;           // 1024 float4
        int c = idx4 >> 4, j4 = (idx4 & 15) * 4;
        float4 v = *(const float4*)(x + (size_t)(b * CC + c) * NN + n0 + j4);
        Xsh[(j4 + 0) * 64 + c] = __float2half_rn(v.x);
        Xsh[(j4 + 1) * 64 + c] = __float2half_rn(v.y);
        Xsh[(j4 + 2) * 64 + c] = __float2half_rn(v.z);
        Xsh[(j4 + 3) * 64 + c] = __float2half_rn(v.w);
    }
    cp_wait0();
    __syncthreads();

    // A-fragments for token rows w*16+g, +8
    uint32_t xa[4][4];
    {
        int row = w * 16 + g;
        #pragma unroll
        for (int s = 0; s < 4; s++) {
            xa[s][0] = Xh[row * 32 + 8 * s + tau];
            xa[s][1] = Xh[(row + 8) * 32 + 8 * s + tau];
            xa[s][2] = Xh[row * 32 + 8 * s + tau + 4];
            xa[s][3] = Xh[(row + 8) * 32 + 8 * s + tau + 4];
        }
    }

    float acc[3][8][4];
    #pragma unroll
    for (int m = 0; m < 3; m++)
        #pragma unroll
        for (int t = 0; t < 8; t++)
            #pragma unroll
            for (int c = 0; c < 4; c++) acc[m][t][c] = 0.f;

    const uint4* Wp4 = (const uint4*)Wp;
    #pragma unroll
    for (int s = 0; s < 4; s++)
        #pragma unroll
        for (int m = 0; m < 3; m++)
            #pragma unroll
            for (int tp = 0; tp < 4; tp++) {
                uint4 kb = Wp4[m * 512 + (s * 4 + tp) * 32 + lam];
                mma16(acc[m][2 * tp],     xa[s], kb.x, kb.y);
                mma16(acc[m][2 * tp + 1], xa[s], kb.z, kb.w);
            }
    __syncthreads();  // done reading Xh / Wp

    // ---- Q: token-major fp16 global ----
    {
        uint32_t* q32 = (uint32_t*)g_qh;
        size_t r0 = (size_t)(b * NN + n0 + w * 16 + g) * 32;
        size_t r8 = r0 + 8 * 32;
        #pragma unroll
        for (int t = 0; t < 8; t++) {
            float2 bb = *(const float2*)(bq + 8 * t + 2 * tau);
            q32[r0 + 4 * t + tau] = h2(acc[0][t][0] + bb.x, acc[0][t][1] + bb.y);
            q32[r8 + 4 * t + tau] = h2(acc[0][t][2] + bb.x, acc[0][t][3] + bb.y);
        }
    }

    // ---- K/V repack into SMEM, then coalesced copy out ----
    uint32_t* KPu = smu;                       // 2048 u32
    __half*  VPh  = (__half*)(smu + 2048);     // 2048 u32 region
    #pragma unroll
    for (int t = 0; t < 8; t++) {
        float2 bk2 = *(const float2*)(bk + 8 * t + 2 * tau);
        int kbase = (((t >> 1) * 4 + w) * 32 + 4 * g + tau) * 4 + (t & 1);
        KPu[kbase + 0] = h2(acc[1][t][0] + bk2.x, acc[1][t][1] + bk2.y);  // row r
        KPu[kbase + 2] = h2(acc[1][t][2] + bk2.x, acc[1][t][3] + bk2.y);  // row r+8
        float2 bv2 = *(const float2*)(bv + 8 * t + 2 * tau);
        int lam0 = 8 * tau + ((g >> 1) & 3);
        int ua = ((w * 4 + (t >> 1)) * 32 + lam0) * 4 + (t & 1) * 2;
        int hsel = g & 1;
        VPh[(ua +  0) * 2 + hsel] = __float2half_rn(acc[2][t][0] + bv2.x);
        VPh[(ua + 16) * 2 + hsel] = __float2half_rn(acc[2][t][1] + bv2.y);
        VPh[(ua +  1) * 2 + hsel] = __float2half_rn(acc[2][t][2] + bv2.x);
        VPh[(ua + 17) * 2 + hsel] = __float2half_rn(acc[2][t][3] + bv2.y);
    }
    __syncthreads();
    {
        const uint4* ks = (const uint4*)KPu;
        const uint4* vs = (const uint4*)VPh;
        uint4* kdst = (uint4*)(g_kph + (size_t)(b * NTILE + tile) * 2048);
        uint4* vdst = (uint4*)(g_vph + (size_t)(b * NTILE + tile) * 2048);
        #pragma unroll
        for (int r = 0; r < 4; r++) {
            int i = tid + 128 * r;
            kdst[i] = ks[i];
            vdst[i] = vs[i];
        }
    }
}

// ---------------------------------------------------------------------------
// Kernel 2: fp16 m16n8k16 flash attention, split-KV, double-buffered cp.async.
// SMEM (u32): Kb[2][2048] | Vb[2][2048] = 32 KB
// ---------------------------------------------------------------------------
__global__ void __launch_bounds__(128, 2) attn_mma_kernel()
{
    extern __shared__ uint32_t smu[];
    uint32_t* Kb = smu;           // 2 x 2048
    uint32_t* Vb = smu + 4096;    // 2 x 2048

    const int b  = blockIdx.y;
    const int q0 = blockIdx.x * TQa;
    const int sp = blockIdx.z;
    const int tid = threadIdx.x, w = tid >> 5, lam = tid & 31;
    const int g = lam >> 2, tau = lam & 3;
    const uint32_t smK = smem_u32(Kb), smV = smem_u32(Vb);
    const float SC = 1.4426950408889634f / (float)NN;  // log2(e)/N

    // ---- Q A-fragments in registers ----
    uint32_t qa[2][4][4];
    {
        const uint32_t* q32 = (const uint32_t*)g_qh;
        #pragma unroll
        for (int m = 0; m < 2; m++) {
            size_t rg  = (size_t)(b * NN + q0 + w * 32 + m * 16 + g) * 32;
            size_t rg8 = rg + 8 * 32;
            #pragma unroll
            for (int s = 0; s < 4; s++) {
                qa[m][s][0] = q32[rg  + 8 * s + tau];
                qa[m][s][1] = q32[rg8 + 8 * s + tau];
                qa[m][s][2] = q32[rg  + 8 * s + tau + 4];
                qa[m][s][3] = q32[rg8 + 8 * s + tau + 4];
            }
        }
    }

    float of[2][8][4];
    #pragma unroll
    for (int m = 0; m < 2; m++)
        #pragma unroll
        for (int t = 0; t < 8; t++)
            #pragma unroll
            for (int c = 0; c < 4; c++) of[m][t][c] = 0.f;
    float lA[2] = {0.f, 0.f};
    float lB[2] = {0.f, 0.f};

    const uint32_t* kp = g_kph + ((size_t)b * NTILE + sp * TPS) * 2048;
    const uint32_t* vp = g_vph + ((size_t)b * NTILE + sp * TPS) * 2048;

    #pragma unroll
    for (int r = 0; r < 4; r++) {
        int i = tid + 128 * r;
        cp16(smK + i * 16, kp + i * 4);
        cp16(smV + i * 16, vp + i * 4);
    }
    cp_commit();

    for (int kt = 0; kt < TPS; kt++) {
        cp_wait0();
        __syncthreads();
        if (kt + 1 < TPS) {
            uint32_t nbb = (uint32_t)((kt + 1) & 1) * 8192u;
            const uint32_t* ksrc = kp + (size_t)(kt + 1) * 2048;
            const uint32_t* vsrc = vp + (size_t)(kt + 1) * 2048;
            #pragma unroll
            for (int r = 0; r < 4; r++) {
                int i = tid + 128 * r;
                cp16(smK + nbb + i * 16, ksrc + i * 4);
                cp16(smV + nbb + i * 16, vsrc + i * 4);
            }
            cp_commit();
        }

        const uint4* Kp4 = (const uint4*)(Kb + (kt & 1) * 2048);
        const uint4* Vp4 = (const uint4*)(Vb + (kt & 1) * 2048);

        // ---- MMA1: S = Q K^T ----
        float sf[2][8][4];
        #pragma unroll
        for (int m = 0; m < 2; m++)
            #pragma unroll
            for (int t = 0; t < 8; t++)
                #pragma unroll
                for (int c = 0; c < 4; c++) sf[m][t][c] = 0.f;

        #pragma unroll
        for (int s = 0; s < 4; s++)
            #pragma unroll
            for (int tp = 0; tp < 4; tp++) {
                uint4 kb = Kp4[(s * 4 + tp) * 32 + lam];
                mma16(sf[0][2 * tp],     qa[0][s], kb.x, kb.y);
                mma16(sf[0][2 * tp + 1], qa[0][s], kb.z, kb.w);
                mma16(sf[1][2 * tp],     qa[1][s], kb.x, kb.y);
                mma16(sf[1][2 * tp + 1], qa[1][s], kb.z, kb.w);
            }

        // ---- softmax ----
        float rs[2][2] = {{0.f, 0.f}, {0.f, 0.f}};
        #pragma unroll
        for (int m = 0; m < 2; m++)
            #pragma unroll
            for (int t = 0; t < 8; t++) {
                float e0 = ex2(sf[m][t][0] * SC);
                float e1 = ex2(sf[m][t][1] * SC);
                float e2 = ex2(sf[m][t][2] * SC);
                float e3 = ex2(sf[m][t][3] * SC);
                rs[m][0] += e0 + e1;
                rs[m][1] += e2 + e3;
                sf[m][t][0] = e0; sf[m][t][1] = e1;
                sf[m][t][2] = e2; sf[m][t][3] = e3;
            }
        #pragma unroll
        for (int m = 0; m < 2; m++) {
            float a = rs[m][0], bs = rs[m][1];
            a += __shfl_xor_sync(0xffffffffu, a, 1);
            a += __shfl_xor_sync(0xffffffffu, a, 2);
            bs += __shfl_xor_sync(0xffffffffu, bs, 1);
            bs += __shfl_xor_sync(0xffffffffu, bs, 2);
            lA[m] += a;
            lB[m] += bs;
        }

        // P A-fragments: pure cvt
        uint32_t pa[2][4][4];
        #pragma unroll
        for (int m = 0; m < 2; m++)
            #pragma unroll
            for (int s = 0; s < 4; s++) {
                pa[m][s][0] = h2(sf[m][2 * s][0],     sf[m][2 * s][1]);
                pa[m][s][1] = h2(sf[m][2 * s][2],     sf[m][2 * s][3]);
                pa[m][s][2] = h2(sf[m][2 * s + 1][0], sf[m][2 * s + 1][1]);
                pa[m][s][3] = h2(sf[m][2 * s + 1][2], sf[m][2 * s + 1][3]);
            }

        // ---- MMA2: O += P V ----
        #pragma unroll
        for (int s = 0; s < 4; s++)
            #pragma unroll
            for (int tp = 0; tp < 4; tp++) {
                uint4 vb = Vp4[(s * 4 + tp) * 32 + lam];
                mma16(of[0][2 * tp],     pa[0][s], vb.x, vb.y);
                mma16(of[0][2 * tp + 1], pa[0][s], vb.z, vb.w);
                mma16(of[1][2 * tp],     pa[1][s], vb.x, vb.y);
                mma16(of[1][2 * tp + 1], pa[1][s], vb.z, vb.w);
            }
    }

    // ---- epilogue ----
    float* po = g_po + (size_t)(sp * BB + b) * CC * NN;
    float* pl = g_pl + (size_t)(sp * BB + b) * NN;
    #pragma unroll
    for (int m = 0; m < 2; m++)
        #pragma unroll
        for (int t = 0; t < 8; t++) {
            int rowa = q0 + w * 32 + m * 16 + g;
            int col = 8 * t + 2 * tau;
            po[(size_t)col       * NN + rowa]     = of[m][t][0];
            po[(size_t)(col + 1) * NN + rowa]     = of[m][t][1];
            po[(size_t)col       * NN + rowa + 8] = of[m][t][2];
            po[(size_t)(col + 1) * NN + rowa + 8] = of[m][t][3];
        }
    if (tau == 0) {
        #pragma unroll
        for (int m = 0; m < 2; m++) {
            int rowa = q0 + w * 32 + m * 16 + g;
            pl[rowa]     = lA[m];
            pl[rowa + 8] = lB[m];
        }
    }
}

// ---------------------------------------------------------------------------
// Kernel 3: combine partials: out = (O0 + O1) / (l0 + l1).
// 256 blocks x 256 threads; each thread owns 4 independent float4 groups
// (one per batch b = r), all loads issued up front -> MLP ~16.
// ---------------------------------------------------------------------------
__global__ void __launch_bounds__(256) combine_kernel(float* __restrict__ out)
{
    const int t0 = blockIdx.x * 256 + threadIdx.x;   // 0..65535
    const int n = (t0 * 4) & (NN - 1);
    const int coff = (t0 * 4) >> 12;                 // channel block within batch

    float4 a[4], c[4], L0[4], L1[4];
    #pragma unroll
    for (int r = 0; r < 4; r++) {
        int idx = t0 + r * 65536;                    // b == r
        a[r]  = ((const float4*)g_po)[idx];
        c[r]  = ((const float4*)g_po)[BB * CC * NN / 4 + idx];
        L0[r] = *(const float4*)(g_pl + (size_t)r * NN + n);
        L1[r] = *(const float4*)(g_pl + (size_t)(BB + r) * NN + n);
    }
    #pragma unroll
    for (int r = 0; r < 4; r++) {
        float4 o;
        o.x = (a[r].x + c[r].x) / (L0[r].x + L1[r].x);
        o.y = (a[r].y + c[r].y) / (L0[r].y + L1[r].y);
        o.z = (a[r].z + c[r].z) / (L0[r].z + L1[r].z);
        o.w = (a[r].w + c[r].w) / (L0[r].w + L1[r].w);
        ((float4*)out)[t0 + r * 65536] = o;
    }
    (void)coff;
}

// ---------------------------------------------------------------------------
extern "C" void kernel_launch(void* const* d_in, const int* in_sizes, int n_in,
                              void* d_out, int out_size)
{
    const float* x  = (const float*)d_in[0];
    const float* wq = (const float*)d_in[1];
    const float* bq = (const float*)d_in[2];
    const float* wk = (const float*)d_in[3];
    const float* bk = (const float*)d_in[4];
    const float* wv = (const float*)d_in[5];
    const float* bv = (const float*)d_in[6];
    float* out = (float*)d_out;

    const int smem_proj = 8192 * sizeof(uint32_t);          // 32768 B
    const int smem_attn = (4096 + 4096) * sizeof(uint32_t); // 32768 B
    cudaFuncSetAttribute(proj_kernel, cudaFuncAttributeMaxDynamicSharedMemorySize, smem_proj);
    cudaFuncSetAttribute(attn_mma_kernel, cudaFuncAttributeMaxDynamicSharedMemorySize, smem_attn);

    wpack_kernel<<<48, 256>>>(wq, wk, wv);
    dim3 gp(NN / 64, BB);
    proj_kernel<<<gp, 128, smem_proj>>>(x, bq, bk, bv);
    dim3 ga(NN / TQa, BB, NSPLIT);
    attn_mma_kernel<<<ga, 128, smem_attn>>>();
    combine_kernel<<<256, 256>>>(out);
}